// round 15
// baseline (speedup 1.0000x reference)
#include <cuda_runtime.h>
#include <cuda_fp16.h>
#include <cstdint>

#define BB 4
#define HH 8
#define SEQ 2048
#define DM 512
#define DH 64
#define BHN (BB*HH)
#define QT 128
#define KT 64
#define NIT (SEQ/KT)
#define TEN ((size_t)BB*SEQ*DM)

// ---------------- scratch ---------------------------------------------------
__device__ __half g_inh[3][TEN];                   // inputs Q/K/V in fp16
__device__ __half g_Wth[4][DM*DM];                 // W^T in fp16: [n][k]
__device__ __half g_Qh[(size_t)BHN*SEQ*DH];        // [bh][s][d]  (d pair-permuted)
__device__ __half g_Kh[(size_t)BHN*SEQ*DH];        // [bh][s][d]  (d pair-permuted)
__device__ __half g_Vt[(size_t)BHN*DH*SEQ];        // [bh][d][s]  (s pair-permuted)
__device__ __half g_ctxh[TEN];                     // fp16 ctx
__device__ float g_tmp[BB*SEQ*DM];                 // fc output (fp32) for LN
__device__ unsigned g_mbits[(size_t)BB*SEQ*(SEQ/32)];

// ---------------- helpers ----------------------------------------------------
__device__ __forceinline__ void mma16n8k16f16(float* d, const uint32_t* a, uint32_t b0, uint32_t b1) {
    asm volatile("mma.sync.aligned.m16n8k16.row.col.f32.f16.f16.f32 "
                 "{%0,%1,%2,%3}, {%4,%5,%6,%7}, {%8,%9}, {%0,%1,%2,%3};"
                 : "+f"(d[0]), "+f"(d[1]), "+f"(d[2]), "+f"(d[3])
                 : "r"(a[0]), "r"(a[1]), "r"(a[2]), "r"(a[3]), "r"(b0), "r"(b1));
}
__device__ __forceinline__ void cpa16(void* s, const void* g) {
    uint32_t sa = (uint32_t)__cvta_generic_to_shared(s);
    asm volatile("cp.async.cg.shared.global [%0], [%1], 16;" :: "r"(sa), "l"(g) : "memory");
}
#define CPA_COMMIT() asm volatile("cp.async.commit_group;" ::: "memory")
#define CPA_WAIT(n)  asm volatile("cp.async.wait_group %0;" :: "n"(n) : "memory")
__device__ __forceinline__ uint32_t packh2(float lo, float hi) {
    __half2 t = __floats2half2_rn(lo, hi);
    return *reinterpret_cast<uint32_t*>(&t);
}
__device__ __forceinline__ int pairperm(int p) {   // word p of 8 -> new slot
    return (p < 4) ? 2 * p : 2 * (p - 4) + 1;
}

// ---------------- mask bit-pack ---------------------------------------------
__global__ __launch_bounds__(256) void pack_mask_kernel(const int* __restrict__ mask) {
    int gw = (blockIdx.x * 256 + threadIdx.x) >> 5;
    int lane = threadIdx.x & 31;
    size_t base = (size_t)gw * 1024;
    unsigned word = 0;
#pragma unroll
    for (int j = 0; j < 32; j++) {
        int v = mask[base + (size_t)j * 32 + lane];
        unsigned bits = __ballot_sync(0xffffffffu, v != 0);
        if (lane == j) word = bits;
    }
    g_mbits[(size_t)gw * 32 + lane] = word;
}

// ---------------- fp32 -> fp16 input conversion (3 tensors, one launch) ------
__global__ __launch_bounds__(256) void conv_h3_kernel(const float4* __restrict__ x0,
                                                      const float4* __restrict__ x1,
                                                      const float4* __restrict__ x2) {
    const float4* x = (blockIdx.y == 0) ? x0 : (blockIdx.y == 1) ? x1 : x2;
    __half2* y = (__half2*)&g_inh[blockIdx.y][0];
    int i = blockIdx.x * 256 + threadIdx.x;
    float4 v = x[i];
    y[2 * i]     = __floats2half2_rn(v.x, v.y);
    y[2 * i + 1] = __floats2half2_rn(v.z, v.w);
}

// ---------------- W transpose+convert (4 weights, one launch) ----------------
__global__ void wtrans_kernel(const float* __restrict__ W0, const float* __restrict__ W1,
                              const float* __restrict__ W2, const float* __restrict__ W3) {
    const float* W = (blockIdx.z == 0) ? W0 : (blockIdx.z == 1) ? W1
                   : (blockIdx.z == 2) ? W2 : W3;
    __half* Wt = &g_Wth[blockIdx.z][0];
    __shared__ float t[32][33];
    int bx = blockIdx.x * 32, by = blockIdx.y * 32;
    int tx = threadIdx.x, ty = threadIdx.y;   // 32 x 8
#pragma unroll
    for (int j = 0; j < 4; j++)
        t[ty + j * 8][tx] = W[(size_t)(by + ty + j * 8) * DM + bx + tx];
    __syncthreads();
#pragma unroll
    for (int j = 0; j < 4; j++)
        Wt[(size_t)(bx + ty + j * 8) * DM + by + tx] = __float2half_rn(t[tx][ty + j * 8]);
}

// ---------------- GEMM fp16 m16n8k16 (mode<0: QKV via blockIdx.z) ------------
__global__ __launch_bounds__(256, 2) void gemm_f16_kernel(int mode) {
    const int md = (mode < 0) ? (int)blockIdx.z : mode;
    const __half* Asrc = (md == 3) ? g_ctxh : &g_inh[md][0];
    const __half* Wt = &g_Wth[md][0];
    __shared__ __half Ash[2][128][40];
    __shared__ __half Bsh[2][128][40];

    const int tid = threadIdx.x;
    const int wid = tid >> 5, lane = tid & 31;
    const int g = lane >> 2, t = lane & 3;
    const int wm = (wid & 3) * 32;
    const int wn = (wid >> 2) * 64;
    const int m0 = blockIdx.y * 128, n0 = blockIdx.x * 128;

    const int arow = tid >> 1, asb = (tid & 1) * 2;
    const __half* ApA = Asrc + (size_t)(m0 + arow) * DM + asb * 8;
    const __half* ApB = Wt   + (size_t)(n0 + arow) * DM + asb * 8;

    float Cc[2][8][4];
#pragma unroll
    for (int i = 0; i < 2; i++)
#pragma unroll
        for (int nn = 0; nn < 8; nn++)
#pragma unroll
            for (int r = 0; r < 4; r++) Cc[i][nn][r] = 0.f;

#pragma unroll
    for (int u = 0; u < 2; u++) {
        cpa16(&Ash[0][arow][(asb + u) * 8], ApA + u * 8);
        cpa16(&Bsh[0][arow][(asb + u) * 8], ApB + u * 8);
    }
    CPA_COMMIT();

    for (int it = 0; it < DM / 32; it++) {
        const int cur = it & 1;
        if (it + 1 < DM / 32) {
            const int nxt = cur ^ 1;
            const int k0n = (it + 1) * 32;
#pragma unroll
            for (int u = 0; u < 2; u++) {
                cpa16(&Ash[nxt][arow][(asb + u) * 8], ApA + k0n + u * 8);
                cpa16(&Bsh[nxt][arow][(asb + u) * 8], ApB + k0n + u * 8);
            }
            CPA_COMMIT();
            CPA_WAIT(1);
        } else {
            CPA_WAIT(0);
        }
        __syncthreads();

        const uint32_t* Aw = (const uint32_t*)Ash[cur];
        const uint32_t* Bw = (const uint32_t*)Bsh[cur];
#pragma unroll
        for (int kk = 0; kk < 2; kk++) {
            const int kb = kk * 8;
            uint32_t a[2][4];
#pragma unroll
            for (int i = 0; i < 2; i++) {
                int rbase = (wm + i * 16 + g) * 20;
                a[i][0] = Aw[rbase + kb + t];
                a[i][1] = Aw[rbase + 160 + kb + t];
                a[i][2] = Aw[rbase + kb + t + 4];
                a[i][3] = Aw[rbase + 160 + kb + t + 4];
            }
#pragma unroll
            for (int nn = 0; nn < 8; nn++) {
                uint32_t b0 = Bw[(wn + nn * 8 + g) * 20 + kb + t];
                uint32_t b1 = Bw[(wn + nn * 8 + g) * 20 + kb + t + 4];
#pragma unroll
                for (int i = 0; i < 2; i++) mma16n8k16f16(Cc[i][nn], a[i], b0, b1);
            }
        }
        __syncthreads();
    }

    const int hbase = n0 >> 6;
#pragma unroll
    for (int i = 0; i < 2; i++) {
#pragma unroll
        for (int rr = 0; rr < 2; rr++) {
            int m = m0 + wm + i * 16 + g + rr * 8;
            int bidx = m >> 11, s = m & 2047;
#pragma unroll
            for (int nn = 0; nn < 8; nn++) {
                int coln = wn + nn * 8 + 2 * t;
                float2 v = make_float2(Cc[i][nn][rr * 2 + 0], Cc[i][nn][rr * 2 + 1]);
                if (md == 3) {
                    *(float2*)&g_tmp[(size_t)m * DM + n0 + coln] = v;
                } else {
                    int hh = hbase + (coln >> 6);
                    int d = coln & 63;
                    int bh = bidx * HH + hh;
                    if (md == 2) {
                        int sp = (s & ~15) | (pairperm((s >> 1) & 7) << 1) | (s & 1);
                        g_Vt[((size_t)bh * DH + d)     * SEQ + sp] = __float2half_rn(v.x);
                        g_Vt[((size_t)bh * DH + d + 1) * SEQ + sp] = __float2half_rn(v.y);
                    } else {
                        int dn = (d & ~15) | (pairperm((d >> 1) & 7) << 1);
                        __half2 hv = __floats2half2_rn(v.x, v.y);
                        __half* dst = (md == 0) ? g_Qh : g_Kh;
                        *(__half2*)&dst[((size_t)bh * SEQ + s) * DH + dn] = hv;
                    }
                }
            }
        }
    }
}

// ---------------- fp16 attention, two-pass, chunk-fused, occ 3 ---------------
#define QROWH 80
#define K_OFF  (128 * QROWH)
#define TILE_H (64 * QROWH)
#define V_OFF  (K_OFF + 2 * TILE_H)
#define SMEM_ATTN ((128 * QROWH + 4 * 64 * QROWH) * 2)   // 61440 B -> 3 CTAs/SM
__global__ __launch_bounds__(256, 3) void attn_mma_kernel(float* __restrict__ attn_out) {
    extern __shared__ __half smh[];

    const int tid  = threadIdx.x;
    const int lane = tid & 31;
    const int gid  = lane >> 2;
    const int cL   = lane & 3;
    const int bh   = blockIdx.y;
    const int b    = bh >> 3, h = bh & 7;
    const int q0   = blockIdx.x * QT;
    const int lr   = (tid >> 5) * 16 + gid;

    const __half* Qg = g_Qh + (size_t)bh * SEQ * DH;
    const __half* Kg = g_Kh + (size_t)bh * SEQ * DH;
    const __half* Vg = g_Vt + (size_t)bh * DH * SEQ;

    // stage Q tile [128][64h]
#pragma unroll
    for (int j = 0; j < 4; j++) {
        int flat = j * 256 + tid;
        int row = flat >> 3, seg = flat & 7;
        cpa16(&smh[row * QROWH + seg * 8], Qg + (size_t)(q0 + row) * DH + seg * 8);
    }
    CPA_COMMIT();
    CPA_WAIT(0);
    __syncthreads();

    uint32_t qa[4][4];
    {
        const uint2* Q2 = (const uint2*)smh;
#pragma unroll
        for (int kk = 0; kk < 4; kk++) {
            uint2 r0 = Q2[lr * 20 + kk * 4 + cL];
            uint2 r1 = Q2[(lr + 8) * 20 + kk * 4 + cL];
            qa[kk][0] = r0.x; qa[kk][1] = r1.x;
            qa[kk][2] = r0.y; qa[kk][3] = r1.y;
        }
    }

    const size_t mrow0 = ((size_t)b * SEQ + q0 + lr) * (SEQ / 32);
    const size_t mrow1 = ((size_t)b * SEQ + q0 + lr + 8) * (SEQ / 32);
    float* aprow0 = attn_out + ((size_t)bh * SEQ + q0 + lr) * SEQ;
    float* aprow1 = aprow0 + 8 * SEQ;

    const int srow = tid >> 2;
    const int sseg = (tid & 3) * 2;
    float lsum0 = 0.f, lsum1 = 0.f;

    // ================= PASS A: lsum only =================
#pragma unroll
    for (int u = 0; u < 2; u++)
        cpa16(&smh[K_OFF + srow * QROWH + (sseg + u) * 8], Kg + (size_t)srow * DH + (sseg + u) * 8);
    CPA_COMMIT();

    for (int i = 0; i < NIT; i++) {
        const int k0 = i * KT;
        const int cur = i & 1;
        if (i + 1 < NIT) {
            const int nxt = cur ^ 1;
            const int kn = k0 + KT;
#pragma unroll
            for (int u = 0; u < 2; u++)
                cpa16(&smh[K_OFF + nxt * TILE_H + srow * QROWH + (sseg + u) * 8],
                      Kg + (size_t)(kn + srow) * DH + (sseg + u) * 8);
            CPA_COMMIT();
            CPA_WAIT(1);
        } else {
            CPA_WAIT(0);
        }
        uint2 m2l = *(const uint2*)&g_mbits[mrow0 + (k0 >> 5)];
        uint2 m2h = *(const uint2*)&g_mbits[mrow1 + (k0 >> 5)];
        __syncthreads();

        const uint2* Kw2 = (const uint2*)(smh + K_OFF + cur * TILE_H);
        unsigned ml[2] = {m2l.x, m2l.y};
        unsigned mh[2] = {m2h.x, m2h.y};

#pragma unroll
        for (int s = 0; s < 4; s++) {
            const int n0i = 2 * s, n1i = 2 * s + 1;
            float S0[4] = {0.f, 0.f, 0.f, 0.f};
            float S1[4] = {0.f, 0.f, 0.f, 0.f};
#pragma unroll
            for (int kk = 0; kk < 4; kk++) {
                uint2 b0 = Kw2[(n0i * 8 + gid) * 20 + kk * 4 + cL];
                uint2 b1 = Kw2[(n1i * 8 + gid) * 20 + kk * 4 + cL];
                mma16n8k16f16(S0, qa[kk], b0.x, b0.y);
                mma16n8k16f16(S1, qa[kk], b1.x, b1.y);
            }
#pragma unroll
            for (int p = 0; p < 2; p++) {
                const int n = 2 * s + p;
                const float* S = p ? S1 : S0;
                int shift = (n & 3) * 8 + 2 * cL;
                unsigned bl  = ml[n >> 2] >> shift;
                unsigned bhh = mh[n >> 2] >> shift;
                lsum0 += ((bl  & 1u) ? 0.f : __expf(S[0] * 0.125f))
                       + ((bl  & 2u) ? 0.f : __expf(S[1] * 0.125f));
                lsum1 += ((bhh & 1u) ? 0.f : __expf(S[2] * 0.125f))
                       + ((bhh & 2u) ? 0.f : __expf(S[3] * 0.125f));
            }
        }
        __syncthreads();
    }

    lsum0 += __shfl_xor_sync(0xffffffffu, lsum0, 1);
    lsum0 += __shfl_xor_sync(0xffffffffu, lsum0, 2);
    lsum1 += __shfl_xor_sync(0xffffffffu, lsum1, 1);
    lsum1 += __shfl_xor_sync(0xffffffffu, lsum1, 2);
    const float inv0 = 1.0f / lsum0;
    const float inv1 = 1.0f / lsum1;

    float Cacc[8][4];
#pragma unroll
    for (int dt = 0; dt < 8; dt++)
#pragma unroll
        for (int r = 0; r < 4; r++) Cacc[dt][r] = 0.f;

    // ================= PASS B: chunk-fused normalized STG + PV =================
#pragma unroll
    for (int u = 0; u < 2; u++) {
        int sg = sseg + u;
        cpa16(&smh[K_OFF + srow * QROWH + sg * 8], Kg + (size_t)srow * DH + sg * 8);
        cpa16(&smh[V_OFF + srow * QROWH + sg * 8], Vg + (size_t)srow * SEQ + sg * 8);
    }
    CPA_COMMIT();

    for (int i = 0; i < NIT; i++) {
        const int k0 = i * KT;
        const int cur = i & 1;
        if (i + 1 < NIT) {
            const int nxt = cur ^ 1;
            const int kn = k0 + KT;
#pragma unroll
            for (int u = 0; u < 2; u++) {
                int sg = sseg + u;
                cpa16(&smh[K_OFF + nxt * TILE_H + srow * QROWH + sg * 8],
                      Kg + (size_t)(kn + srow) * DH + sg * 8);
                cpa16(&smh[V_OFF + nxt * TILE_H + srow * QROWH + sg * 8],
                      Vg + (size_t)srow * SEQ + kn + sg * 8);
            }
            CPA_COMMIT();
            CPA_WAIT(1);
        } else {
            CPA_WAIT(0);
        }
        uint2 m2l = *(const uint2*)&g_mbits[mrow0 + (k0 >> 5)];
        uint2 m2h = *(const uint2*)&g_mbits[mrow1 + (k0 >> 5)];
        __syncthreads();

        const uint2* Kw2 = (const uint2*)(smh + K_OFF + cur * TILE_H);
        const uint2* Vw2 = (const uint2*)(smh + V_OFF + cur * TILE_H);
        unsigned ml[2] = {m2l.x, m2l.y};
        unsigned mh[2] = {m2h.x, m2h.y};

#pragma unroll
        for (int s = 0; s < 4; s++) {
            const int n0i = 2 * s, n1i = 2 * s + 1;
            float S0[4] = {0.f, 0.f, 0.f, 0.f};
            float S1[4] = {0.f, 0.f, 0.f, 0.f};
#pragma unroll
            for (int kk = 0; kk < 4; kk++) {
                uint2 b0 = Kw2[(n0i * 8 + gid) * 20 + kk * 4 + cL];
                uint2 b1 = Kw2[(n1i * 8 + gid) * 20 + kk * 4 + cL];
                mma16n8k16f16(S0, qa[kk], b0.x, b0.y);
                mma16n8k16f16(S1, qa[kk], b1.x, b1.y);
            }
            uint32_t pa[4];
#pragma unroll
            for (int p = 0; p < 2; p++) {
                const int n = 2 * s + p;
                const float* S = p ? S1 : S0;
                int shift = (n & 3) * 8 + 2 * cL;
                unsigned bl  = ml[n >> 2] >> shift;
                unsigned bhh = mh[n >> 2] >> shift;
                float e0 = (bl  & 1u) ? 0.f : __expf(S[0] * 0.125f) * inv0;
                float e1 = (bl  & 2u) ? 0.f : __expf(S[1] * 0.125f) * inv0;
                float e2 = (bhh & 1u) ? 0.f : __expf(S[2] * 0.125f) * inv1;
                float e3 = (bhh & 2u) ? 0.f : __expf(S[3] * 0.125f) * inv1;
                int col = k0 + n * 8 + 2 * cL;
                *(float2*)(aprow0 + col) = make_float2(e0, e1);
                *(float2*)(aprow1 + col) = make_float2(e2, e3);
                pa[2 * p]     = packh2(e0, e1);
                pa[2 * p + 1] = packh2(e2, e3);
            }
#pragma unroll
            for (int dt = 0; dt < 8; dt++) {
                uint2 vv = Vw2[(dt * 8 + gid) * 20 + s * 4 + cL];
                mma16n8k16f16(Cacc[dt], pa, vv.x, vv.y);
            }
        }
        __syncthreads();
    }

    __half* cp0 = g_ctxh + ((size_t)b * SEQ + q0 + lr) * DM + h * DH;
    __half* cp1 = cp0 + 8 * DM;
#pragma unroll
    for (int dt = 0; dt < 8; dt++) {
        int col = dt * 8 + 2 * cL;
        *(__half2*)&cp0[col] = __floats2half2_rn(Cacc[dt][0], Cacc[dt][1]);
        *(__half2*)&cp1[col] = __floats2half2_rn(Cacc[dt][2], Cacc[dt][3]);
    }
}

// ---------------- layernorm(tmp + input_Q) ----------------------------------
__global__ __launch_bounds__(256) void ln_kernel(const float* __restrict__ inQ,
                                                 const float* __restrict__ gamma,
                                                 const float* __restrict__ beta,
                                                 float* __restrict__ out) {
    int row = blockIdx.x;
    int tid = threadIdx.x;
    const float* t  = g_tmp + (size_t)row * DM;
    const float* xq = inQ  + (size_t)row * DM;
    float2 a  = *(const float2*)(t  + tid * 2);
    float2 b2 = *(const float2*)(xq + tid * 2);
    float x0 = a.x + b2.x, x1 = a.y + b2.y;
    float s  = x0 + x1;
    float sq = x0 * x0 + x1 * x1;
#pragma unroll
    for (int o = 16; o; o >>= 1) {
        s  += __shfl_xor_sync(0xffffffffu, s,  o);
        sq += __shfl_xor_sync(0xffffffffu, sq, o);
    }
    __shared__ float ws[8], wq[8];
    int w = tid >> 5, lane = tid & 31;
    if (lane == 0) { ws[w] = s; wq[w] = sq; }
    __syncthreads();
    float ts = 0.f, tq = 0.f;
#pragma unroll
    for (int k = 0; k < 8; k++) { ts += ws[k]; tq += wq[k]; }
    float mu  = ts * (1.f / DM);
    float var = tq * (1.f / DM) - mu * mu;
    float r = rsqrtf(var + 1e-5f);
    float2 g  = *(const float2*)(gamma + tid * 2);
    float2 be = *(const float2*)(beta  + tid * 2);
    float2 o;
    o.x = (x0 - mu) * r * g.x + be.x;
    o.y = (x1 - mu) * r * g.y + be.y;
    *(float2*)(out + (size_t)row * DM + tid * 2) = o;
}

// ---------------- launch ----------------------------------------------------
extern "C" void kernel_launch(void* const* d_in, const int* in_sizes, int n_in,
                              void* d_out, int out_size) {
    const float* inQ  = (const float*)d_in[0];
    const float* inK  = (const float*)d_in[1];
    const float* inV  = (const float*)d_in[2];
    const int*   mask = (const int*)d_in[3];
    const float* WQ   = (const float*)d_in[4];
    const float* WK   = (const float*)d_in[5];
    const float* WV   = (const float*)d_in[6];
    const float* Wfc  = (const float*)d_in[7];
    const float* gamma = (const float*)d_in[8];
    const float* beta  = (const float*)d_in[9];

    float* out = (float*)d_out;
    const long OUT_ELEMS = (long)BB * SEQ * DM;
    float* attn_out = out + OUT_ELEMS;

    pack_mask_kernel<<<2048, 256>>>(mask);
    conv_h3_kernel<<<dim3(4096, 3), 256>>>((const float4*)inQ, (const float4*)inK, (const float4*)inV);
    wtrans_kernel<<<dim3(16, 16, 4), dim3(32, 8)>>>(WQ, WK, WV, Wfc);

    gemm_f16_kernel<<<dim3(4, 64, 3), 256>>>(-1);        // QKV fused

    cudaFuncSetAttribute(attn_mma_kernel, cudaFuncAttributeMaxDynamicSharedMemorySize, SMEM_ATTN);
    attn_mma_kernel<<<dim3(SEQ / QT, BHN), 256, SMEM_ATTN>>>(attn_out);

    gemm_f16_kernel<<<dim3(4, 64), 256>>>(3);            // fc
    ln_kernel<<<BB * SEQ, 256>>>(inQ, gamma, beta, out);
}

// round 16
// speedup vs baseline: 1.0049x; 1.0049x over previous
#include <cuda_runtime.h>
#include <cuda_fp16.h>
#include <cstdint>

#define BB 4
#define HH 8
#define SEQ 2048
#define DM 512
#define DH 64
#define BHN (BB*HH)
#define QT 128
#define KT 64
#define NIT (SEQ/KT)
#define KTA 128
#define NITA (SEQ/KTA)
#define TEN ((size_t)BB*SEQ*DM)

// ---------------- scratch ---------------------------------------------------
__device__ __half g_inh[3][TEN];                   // inputs Q/K/V in fp16
__device__ __half g_Wth[4][DM*DM];                 // W^T in fp16: [n][k]
__device__ __half g_Qh[(size_t)BHN*SEQ*DH];        // [bh][s][d]  (d pair-permuted)
__device__ __half g_Kh[(size_t)BHN*SEQ*DH];        // [bh][s][d]  (d pair-permuted)
__device__ __half g_Vt[(size_t)BHN*DH*SEQ];        // [bh][d][s]  (s pair-permuted)
__device__ __half g_ctxh[TEN];                     // fp16 ctx
__device__ float g_tmp[BB*SEQ*DM];                 // fc output (fp32) for LN
__device__ unsigned g_mbits[(size_t)BB*SEQ*(SEQ/32)];

// ---------------- helpers ----------------------------------------------------
__device__ __forceinline__ void mma16n8k16f16(float* d, const uint32_t* a, uint32_t b0, uint32_t b1) {
    asm volatile("mma.sync.aligned.m16n8k16.row.col.f32.f16.f16.f32 "
                 "{%0,%1,%2,%3}, {%4,%5,%6,%7}, {%8,%9}, {%0,%1,%2,%3};"
                 : "+f"(d[0]), "+f"(d[1]), "+f"(d[2]), "+f"(d[3])
                 : "r"(a[0]), "r"(a[1]), "r"(a[2]), "r"(a[3]), "r"(b0), "r"(b1));
}
__device__ __forceinline__ void cpa16(void* s, const void* g) {
    uint32_t sa = (uint32_t)__cvta_generic_to_shared(s);
    asm volatile("cp.async.cg.shared.global [%0], [%1], 16;" :: "r"(sa), "l"(g) : "memory");
}
#define CPA_COMMIT() asm volatile("cp.async.commit_group;" ::: "memory")
#define CPA_WAIT(n)  asm volatile("cp.async.wait_group %0;" :: "n"(n) : "memory")
__device__ __forceinline__ uint32_t packh2(float lo, float hi) {
    __half2 t = __floats2half2_rn(lo, hi);
    return *reinterpret_cast<uint32_t*>(&t);
}
__device__ __forceinline__ int pairperm(int p) {   // word p of 8 -> new slot
    return (p < 4) ? 2 * p : 2 * (p - 4) + 1;
}

// ---------------- mask bit-pack ---------------------------------------------
__global__ __launch_bounds__(256) void pack_mask_kernel(const int* __restrict__ mask) {
    int gw = (blockIdx.x * 256 + threadIdx.x) >> 5;
    int lane = threadIdx.x & 31;
    size_t base = (size_t)gw * 1024;
    unsigned word = 0;
#pragma unroll
    for (int j = 0; j < 32; j++) {
        int v = mask[base + (size_t)j * 32 + lane];
        unsigned bits = __ballot_sync(0xffffffffu, v != 0);
        if (lane == j) word = bits;
    }
    g_mbits[(size_t)gw * 32 + lane] = word;
}

// ---------------- fp32 -> fp16 input conversion (3 tensors, one launch) ------
__global__ __launch_bounds__(256) void conv_h3_kernel(const float4* __restrict__ x0,
                                                      const float4* __restrict__ x1,
                                                      const float4* __restrict__ x2) {
    const float4* x = (blockIdx.y == 0) ? x0 : (blockIdx.y == 1) ? x1 : x2;
    __half2* y = (__half2*)&g_inh[blockIdx.y][0];
    int i = blockIdx.x * 256 + threadIdx.x;
    float4 v = x[i];
    y[2 * i]     = __floats2half2_rn(v.x, v.y);
    y[2 * i + 1] = __floats2half2_rn(v.z, v.w);
}

// ---------------- W transpose+convert (4 weights, one launch) ----------------
__global__ void wtrans_kernel(const float* __restrict__ W0, const float* __restrict__ W1,
                              const float* __restrict__ W2, const float* __restrict__ W3) {
    const float* W = (blockIdx.z == 0) ? W0 : (blockIdx.z == 1) ? W1
                   : (blockIdx.z == 2) ? W2 : W3;
    __half* Wt = &g_Wth[blockIdx.z][0];
    __shared__ float t[32][33];
    int bx = blockIdx.x * 32, by = blockIdx.y * 32;
    int tx = threadIdx.x, ty = threadIdx.y;   // 32 x 8
#pragma unroll
    for (int j = 0; j < 4; j++)
        t[ty + j * 8][tx] = W[(size_t)(by + ty + j * 8) * DM + bx + tx];
    __syncthreads();
#pragma unroll
    for (int j = 0; j < 4; j++)
        Wt[(size_t)(bx + ty + j * 8) * DM + by + tx] = __float2half_rn(t[tx][ty + j * 8]);
}

// ---------------- GEMM fp16 m16n8k16 (mode<0: QKV via blockIdx.z) ------------
__global__ __launch_bounds__(256, 2) void gemm_f16_kernel(int mode) {
    const int md = (mode < 0) ? (int)blockIdx.z : mode;
    const __half* Asrc = (md == 3) ? g_ctxh : &g_inh[md][0];
    const __half* Wt = &g_Wth[md][0];
    __shared__ __half Ash[2][128][40];
    __shared__ __half Bsh[2][128][40];

    const int tid = threadIdx.x;
    const int wid = tid >> 5, lane = tid & 31;
    const int g = lane >> 2, t = lane & 3;
    const int wm = (wid & 3) * 32;
    const int wn = (wid >> 2) * 64;
    const int m0 = blockIdx.y * 128, n0 = blockIdx.x * 128;

    const int arow = tid >> 1, asb = (tid & 1) * 2;
    const __half* ApA = Asrc + (size_t)(m0 + arow) * DM + asb * 8;
    const __half* ApB = Wt   + (size_t)(n0 + arow) * DM + asb * 8;

    float Cc[2][8][4];
#pragma unroll
    for (int i = 0; i < 2; i++)
#pragma unroll
        for (int nn = 0; nn < 8; nn++)
#pragma unroll
            for (int r = 0; r < 4; r++) Cc[i][nn][r] = 0.f;

#pragma unroll
    for (int u = 0; u < 2; u++) {
        cpa16(&Ash[0][arow][(asb + u) * 8], ApA + u * 8);
        cpa16(&Bsh[0][arow][(asb + u) * 8], ApB + u * 8);
    }
    CPA_COMMIT();

    for (int it = 0; it < DM / 32; it++) {
        const int cur = it & 1;
        if (it + 1 < DM / 32) {
            const int nxt = cur ^ 1;
            const int k0n = (it + 1) * 32;
#pragma unroll
            for (int u = 0; u < 2; u++) {
                cpa16(&Ash[nxt][arow][(asb + u) * 8], ApA + k0n + u * 8);
                cpa16(&Bsh[nxt][arow][(asb + u) * 8], ApB + k0n + u * 8);
            }
            CPA_COMMIT();
            CPA_WAIT(1);
        } else {
            CPA_WAIT(0);
        }
        __syncthreads();

        const uint32_t* Aw = (const uint32_t*)Ash[cur];
        const uint32_t* Bw = (const uint32_t*)Bsh[cur];
#pragma unroll
        for (int kk = 0; kk < 2; kk++) {
            const int kb = kk * 8;
            uint32_t a[2][4];
#pragma unroll
            for (int i = 0; i < 2; i++) {
                int rbase = (wm + i * 16 + g) * 20;
                a[i][0] = Aw[rbase + kb + t];
                a[i][1] = Aw[rbase + 160 + kb + t];
                a[i][2] = Aw[rbase + kb + t + 4];
                a[i][3] = Aw[rbase + 160 + kb + t + 4];
            }
#pragma unroll
            for (int nn = 0; nn < 8; nn++) {
                uint32_t b0 = Bw[(wn + nn * 8 + g) * 20 + kb + t];
                uint32_t b1 = Bw[(wn + nn * 8 + g) * 20 + kb + t + 4];
#pragma unroll
                for (int i = 0; i < 2; i++) mma16n8k16f16(Cc[i][nn], a[i], b0, b1);
            }
        }
        __syncthreads();
    }

    const int hbase = n0 >> 6;
#pragma unroll
    for (int i = 0; i < 2; i++) {
#pragma unroll
        for (int rr = 0; rr < 2; rr++) {
            int m = m0 + wm + i * 16 + g + rr * 8;
            int bidx = m >> 11, s = m & 2047;
#pragma unroll
            for (int nn = 0; nn < 8; nn++) {
                int coln = wn + nn * 8 + 2 * t;
                float2 v = make_float2(Cc[i][nn][rr * 2 + 0], Cc[i][nn][rr * 2 + 1]);
                if (md == 3) {
                    *(float2*)&g_tmp[(size_t)m * DM + n0 + coln] = v;
                } else {
                    int hh = hbase + (coln >> 6);
                    int d = coln & 63;
                    int bh = bidx * HH + hh;
                    if (md == 2) {
                        int sp = (s & ~15) | (pairperm((s >> 1) & 7) << 1) | (s & 1);
                        g_Vt[((size_t)bh * DH + d)     * SEQ + sp] = __float2half_rn(v.x);
                        g_Vt[((size_t)bh * DH + d + 1) * SEQ + sp] = __float2half_rn(v.y);
                    } else {
                        int dn = (d & ~15) | (pairperm((d >> 1) & 7) << 1);
                        __half2 hv = __floats2half2_rn(v.x, v.y);
                        __half* dst = (md == 0) ? g_Qh : g_Kh;
                        *(__half2*)&dst[((size_t)bh * SEQ + s) * DH + dn] = hv;
                    }
                }
            }
        }
    }
}

// ---------------- fp16 attention, two-pass, 40KB smem -> true occ 3 ----------
// Q staged transiently (region reused by K/V ring). Pass A: KT=128, K-only ring.
// Pass B: KT=64, K+V ring.  Rows stride 80 halves.
#define QROWH 80
#define HTILE (64 * QROWH)                // 5120 halves = 10240 B
#define SMEM_ATTN (4 * HTILE * 2)         // 40960 B
__global__ __launch_bounds__(256, 3) void attn_mma_kernel(float* __restrict__ attn_out) {
    extern __shared__ __half smh[];

    const int tid  = threadIdx.x;
    const int lane = tid & 31;
    const int gid  = lane >> 2;
    const int cL   = lane & 3;
    const int bh   = blockIdx.y;
    const int b    = bh >> 3, h = bh & 7;
    const int q0   = blockIdx.x * QT;
    const int lr   = (tid >> 5) * 16 + gid;

    const __half* Qg = g_Qh + (size_t)bh * SEQ * DH;
    const __half* Kg = g_Kh + (size_t)bh * SEQ * DH;
    const __half* Vg = g_Vt + (size_t)bh * DH * SEQ;

    // stage Q tile [128][64h] into smem transiently
#pragma unroll
    for (int j = 0; j < 4; j++) {
        int flat = j * 256 + tid;
        int row = flat >> 3, seg = flat & 7;
        cpa16(&smh[row * QROWH + seg * 8], Qg + (size_t)(q0 + row) * DH + seg * 8);
    }
    CPA_COMMIT();
    CPA_WAIT(0);
    __syncthreads();

    uint32_t qa[4][4];
    {
        const uint2* Q2 = (const uint2*)smh;
#pragma unroll
        for (int kk = 0; kk < 4; kk++) {
            uint2 r0 = Q2[lr * 20 + kk * 4 + cL];
            uint2 r1 = Q2[(lr + 8) * 20 + kk * 4 + cL];
            qa[kk][0] = r0.x; qa[kk][1] = r1.x;
            qa[kk][2] = r0.y; qa[kk][3] = r1.y;
        }
    }
    __syncthreads();   // Q reads complete before the ring overwrites the region

    const size_t mrow0 = ((size_t)b * SEQ + q0 + lr) * (SEQ / 32);
    const size_t mrow1 = ((size_t)b * SEQ + q0 + lr + 8) * (SEQ / 32);
    float* aprow0 = attn_out + ((size_t)bh * SEQ + q0 + lr) * SEQ;
    float* aprow1 = aprow0 + 8 * SEQ;

    float lsum0 = 0.f, lsum1 = 0.f;

    // ================= PASS A: KT=128, K-only ring (2 x 128-row tiles) ========
    {
        const int srow = tid >> 1;              // 0..127
        const int sseg = (tid & 1) * 4;         // 4 segs of 8 halves each
#pragma unroll
        for (int u = 0; u < 4; u++)
            cpa16(&smh[srow * QROWH + (sseg + u) * 8], Kg + (size_t)srow * DH + (sseg + u) * 8);
        CPA_COMMIT();

        for (int i = 0; i < NITA; i++) {
            const int k0 = i * KTA;
            const int cur = i & 1;
            if (i + 1 < NITA) {
                const int nxt = cur ^ 1;
                const int kn = k0 + KTA;
#pragma unroll
                for (int u = 0; u < 4; u++)
                    cpa16(&smh[nxt * 2 * HTILE + srow * QROWH + (sseg + u) * 8],
                          Kg + (size_t)(kn + srow) * DH + (sseg + u) * 8);
                CPA_COMMIT();
                CPA_WAIT(1);
            } else {
                CPA_WAIT(0);
            }
            uint4 m4l = *(const uint4*)&g_mbits[mrow0 + (k0 >> 5)];
            uint4 m4h = *(const uint4*)&g_mbits[mrow1 + (k0 >> 5)];
            __syncthreads();

            const uint2* Kw2 = (const uint2*)(smh + cur * 2 * HTILE);
            unsigned ml[4] = {m4l.x, m4l.y, m4l.z, m4l.w};
            unsigned mh[4] = {m4h.x, m4h.y, m4h.z, m4h.w};

#pragma unroll
            for (int s = 0; s < 8; s++) {
                float S0[4] = {0.f, 0.f, 0.f, 0.f};
                float S1[4] = {0.f, 0.f, 0.f, 0.f};
#pragma unroll
                for (int kk = 0; kk < 4; kk++) {
                    uint2 b0 = Kw2[((2 * s) * 8 + gid) * 20 + kk * 4 + cL];
                    uint2 b1 = Kw2[((2 * s + 1) * 8 + gid) * 20 + kk * 4 + cL];
                    mma16n8k16f16(S0, qa[kk], b0.x, b0.y);
                    mma16n8k16f16(S1, qa[kk], b1.x, b1.y);
                }
#pragma unroll
                for (int p = 0; p < 2; p++) {
                    const int n = 2 * s + p;
                    const float* S = p ? S1 : S0;
                    int shift = (n & 3) * 8 + 2 * cL;
                    unsigned bl  = ml[n >> 2] >> shift;
                    unsigned bhh = mh[n >> 2] >> shift;
                    lsum0 += ((bl  & 1u) ? 0.f : __expf(S[0] * 0.125f))
                           + ((bl  & 2u) ? 0.f : __expf(S[1] * 0.125f));
                    lsum1 += ((bhh & 1u) ? 0.f : __expf(S[2] * 0.125f))
                           + ((bhh & 2u) ? 0.f : __expf(S[3] * 0.125f));
                }
            }
            __syncthreads();
        }
    }

    lsum0 += __shfl_xor_sync(0xffffffffu, lsum0, 1);
    lsum0 += __shfl_xor_sync(0xffffffffu, lsum0, 2);
    lsum1 += __shfl_xor_sync(0xffffffffu, lsum1, 1);
    lsum1 += __shfl_xor_sync(0xffffffffu, lsum1, 2);
    const float inv0 = 1.0f / lsum0;
    const float inv1 = 1.0f / lsum1;

    float Cacc[8][4];
#pragma unroll
    for (int dt = 0; dt < 8; dt++)
#pragma unroll
        for (int r = 0; r < 4; r++) Cacc[dt][r] = 0.f;

    // ================= PASS B: KT=64, K+V ring =================
    // layout: K tiles at [0, HTILE), [HTILE, 2*HTILE); V tiles at [2*HTILE, ...)
    {
        const int srow = tid >> 2;
        const int sseg = (tid & 3) * 2;
#pragma unroll
        for (int u = 0; u < 2; u++) {
            int sg = sseg + u;
            cpa16(&smh[srow * QROWH + sg * 8], Kg + (size_t)srow * DH + sg * 8);
            cpa16(&smh[2 * HTILE + srow * QROWH + sg * 8], Vg + (size_t)srow * SEQ + sg * 8);
        }
        CPA_COMMIT();

        for (int i = 0; i < NIT; i++) {
            const int k0 = i * KT;
            const int cur = i & 1;
            if (i + 1 < NIT) {
                const int nxt = cur ^ 1;
                const int kn = k0 + KT;
#pragma unroll
                for (int u = 0; u < 2; u++) {
                    int sg = sseg + u;
                    cpa16(&smh[nxt * HTILE + srow * QROWH + sg * 8],
                          Kg + (size_t)(kn + srow) * DH + sg * 8);
                    cpa16(&smh[(2 + nxt) * HTILE + srow * QROWH + sg * 8],
                          Vg + (size_t)srow * SEQ + kn + sg * 8);
                }
                CPA_COMMIT();
                CPA_WAIT(1);
            } else {
                CPA_WAIT(0);
            }
            uint2 m2l = *(const uint2*)&g_mbits[mrow0 + (k0 >> 5)];
            uint2 m2h = *(const uint2*)&g_mbits[mrow1 + (k0 >> 5)];
            __syncthreads();

            const uint2* Kw2 = (const uint2*)(smh + cur * HTILE);
            const uint2* Vw2 = (const uint2*)(smh + (2 + cur) * HTILE);
            unsigned ml[2] = {m2l.x, m2l.y};
            unsigned mh[2] = {m2h.x, m2h.y};

#pragma unroll
            for (int s = 0; s < 4; s++) {
                float S0[4] = {0.f, 0.f, 0.f, 0.f};
                float S1[4] = {0.f, 0.f, 0.f, 0.f};
#pragma unroll
                for (int kk = 0; kk < 4; kk++) {
                    uint2 b0 = Kw2[((2 * s) * 8 + gid) * 20 + kk * 4 + cL];
                    uint2 b1 = Kw2[((2 * s + 1) * 8 + gid) * 20 + kk * 4 + cL];
                    mma16n8k16f16(S0, qa[kk], b0.x, b0.y);
                    mma16n8k16f16(S1, qa[kk], b1.x, b1.y);
                }
                uint32_t pa[4];
#pragma unroll
                for (int p = 0; p < 2; p++) {
                    const int n = 2 * s + p;
                    const float* S = p ? S1 : S0;
                    int shift = (n & 3) * 8 + 2 * cL;
                    unsigned bl  = ml[n >> 2] >> shift;
                    unsigned bhh = mh[n >> 2] >> shift;
                    float e0 = (bl  & 1u) ? 0.f : __expf(S[0] * 0.125f) * inv0;
                    float e1 = (bl  & 2u) ? 0.f : __expf(S[1] * 0.125f) * inv0;
                    float e2 = (bhh & 1u) ? 0.f : __expf(S[2] * 0.125f) * inv1;
                    float e3 = (bhh & 2u) ? 0.f : __expf(S[3] * 0.125f) * inv1;
                    int col = k0 + n * 8 + 2 * cL;
                    *(float2*)(aprow0 + col) = make_float2(e0, e1);
                    *(float2*)(aprow1 + col) = make_float2(e2, e3);
                    pa[2 * p]     = packh2(e0, e1);
                    pa[2 * p + 1] = packh2(e2, e3);
                }
#pragma unroll
                for (int dt = 0; dt < 8; dt++) {
                    uint2 vv = Vw2[(dt * 8 + gid) * 20 + s * 4 + cL];
                    mma16n8k16f16(Cacc[dt], pa, vv.x, vv.y);
                }
            }
            __syncthreads();
        }
    }

    __half* cp0 = g_ctxh + ((size_t)b * SEQ + q0 + lr) * DM + h * DH;
    __half* cp1 = cp0 + 8 * DM;
#pragma unroll
    for (int dt = 0; dt < 8; dt++) {
        int col = dt * 8 + 2 * cL;
        *(__half2*)&cp0[col] = __floats2half2_rn(Cacc[dt][0], Cacc[dt][1]);
        *(__half2*)&cp1[col] = __floats2half2_rn(Cacc[dt][2], Cacc[dt][3]);
    }
}

// ---------------- layernorm(tmp + input_Q) ----------------------------------
__global__ __launch_bounds__(256) void ln_kernel(const float* __restrict__ inQ,
                                                 const float* __restrict__ gamma,
                                                 const float* __restrict__ beta,
                                                 float* __restrict__ out) {
    int row = blockIdx.x;
    int tid = threadIdx.x;
    const float* t  = g_tmp + (size_t)row * DM;
    const float* xq = inQ  + (size_t)row * DM;
    float2 a  = *(const float2*)(t  + tid * 2);
    float2 b2 = *(const float2*)(xq + tid * 2);
    float x0 = a.x + b2.x, x1 = a.y + b2.y;
    float s  = x0 + x1;
    float sq = x0 * x0 + x1 * x1;
#pragma unroll
    for (int o = 16; o; o >>= 1) {
        s  += __shfl_xor_sync(0xffffffffu, s,  o);
        sq += __shfl_xor_sync(0xffffffffu, sq, o);
    }
    __shared__ float ws[8], wq[8];
    int w = tid >> 5, lane = tid & 31;
    if (lane == 0) { ws[w] = s; wq[w] = sq; }
    __syncthreads();
    float ts = 0.f, tq = 0.f;
#pragma unroll
    for (int k = 0; k < 8; k++) { ts += ws[k]; tq += wq[k]; }
    float mu  = ts * (1.f / DM);
    float var = tq * (1.f / DM) - mu * mu;
    float r = rsqrtf(var + 1e-5f);
    float2 g  = *(const float2*)(gamma + tid * 2);
    float2 be = *(const float2*)(beta  + tid * 2);
    float2 o;
    o.x = (x0 - mu) * r * g.x + be.x;
    o.y = (x1 - mu) * r * g.y + be.y;
    *(float2*)(out + (size_t)row * DM + tid * 2) = o;
}

// ---------------- launch ----------------------------------------------------
extern "C" void kernel_launch(void* const* d_in, const int* in_sizes, int n_in,
                              void* d_out, int out_size) {
    const float* inQ  = (const float*)d_in[0];
    const float* inK  = (const float*)d_in[1];
    const float* inV  = (const float*)d_in[2];
    const int*   mask = (const int*)d_in[3];
    const float* WQ   = (const float*)d_in[4];
    const float* WK   = (const float*)d_in[5];
    const float* WV   = (const float*)d_in[6];
    const float* Wfc  = (const float*)d_in[7];
    const float* gamma = (const float*)d_in[8];
    const float* beta  = (const float*)d_in[9];

    float* out = (float*)d_out;
    const long OUT_ELEMS = (long)BB * SEQ * DM;
    float* attn_out = out + OUT_ELEMS;

    pack_mask_kernel<<<2048, 256>>>(mask);
    conv_h3_kernel<<<dim3(4096, 3), 256>>>((const float4*)inQ, (const float4*)inK, (const float4*)inV);
    wtrans_kernel<<<dim3(16, 16, 4), dim3(32, 8)>>>(WQ, WK, WV, Wfc);

    gemm_f16_kernel<<<dim3(4, 64, 3), 256>>>(-1);        // QKV fused

    attn_mma_kernel<<<dim3(SEQ / QT, BHN), 256, SMEM_ATTN>>>(attn_out);

    gemm_f16_kernel<<<dim3(4, 64), 256>>>(3);            // fc
    ln_kernel<<<BB * SEQ, 256>>>(inQ, gamma, beta, out);
}